// round 11
// baseline (speedup 1.0000x reference)
#include <cuda_runtime.h>
#include <cuda_fp16.h>
#include <math.h>

#define BATCH 8
#define CH    512
#define NPIX  4356          // 66*66 valid pixels
#define MPAD  4752          // 66 rows * 72 padded cols
#define SUP   138
#define KTOT  4608
#define CISZ  5040          // per-ci padded image: 70 rows * 72 cols (halves)
#define BSZ   (512 * CISZ)  // per-batch padded image halves = 2,580,480

typedef unsigned int u32;
typedef unsigned long long u64;

// ---------------- scratch (device globals; zero-initialized) ----------------
__device__ float g_styles[BATCH * CH];
__device__ float g_s[BATCH * CH];
__device__ __align__(16) __half g_xp[3 * BATCH * (size_t)BSZ];    // 3 kx-shifted padded imgs
__device__ __align__(16) __half g_wtB[(size_t)CH * KTOT];         // half(wt) [o][k]
__device__ u32 g_ka[KTOT];                                        // k -> halves offset
__device__ float g_A[CH * CH];
__device__ float g_d[BATCH * CH];
__device__ __align__(16) float g_y[(size_t)BATCH * CH * MPAD];    // conv out [b][o][p']

__device__ __forceinline__ void ldsm4(u32& r0, u32& r1, u32& r2, u32& r3, u32 addr) {
    asm volatile("ldmatrix.sync.aligned.m8n8.x4.shared.b16 {%0,%1,%2,%3}, [%4];"
        : "=r"(r0), "=r"(r1), "=r"(r2), "=r"(r3) : "r"(addr));
}
__device__ __forceinline__ void ldsm4t(u32& r0, u32& r1, u32& r2, u32& r3, u32 addr) {
    asm volatile("ldmatrix.sync.aligned.m8n8.x4.trans.shared.b16 {%0,%1,%2,%3}, [%4];"
        : "=r"(r0), "=r"(r1), "=r"(r2), "=r"(r3) : "r"(addr));
}
__device__ __forceinline__ void mma_f16(float* c, u32 a0, u32 a1, u32 a2, u32 a3,
                                        u32 b0, u32 b1) {
    asm volatile("mma.sync.aligned.m16n8k16.row.col.f32.f16.f16.f32 "
        "{%0,%1,%2,%3}, {%4,%5,%6,%7}, {%8,%9}, {%0,%1,%2,%3};"
        : "+f"(c[0]), "+f"(c[1]), "+f"(c[2]), "+f"(c[3])
        : "r"(a0), "r"(a1), "r"(a2), "r"(a3), "r"(b0), "r"(b1));
}
__device__ __forceinline__ u32 smem_u32(const void* p) {
    u32 a; asm("{ .reg .u64 t; cvta.to.shared.u64 t, %1; cvt.u32.u64 %0, t; }"
               : "=r"(a) : "l"(p));
    return a;
}
__device__ __forceinline__ u64 gmem_u64(const void* p) {
    u64 a; asm("cvta.to.global.u64 %0, %1;" : "=l"(a) : "l"(p));
    return a;
}
__device__ __forceinline__ void cpa16(u32 dst, u64 src) {
    asm volatile("cp.async.cg.shared.global [%0], [%1], 16;"
                 :: "r"(dst), "l"(src) : "memory");
}
__device__ __forceinline__ void cpa_commit() {
    asm volatile("cp.async.commit_group;" ::: "memory");
}
template <int N> __device__ __forceinline__ void cpa_wait() {
    asm volatile("cp.async.wait_group %0;" :: "n"(N) : "memory");
}

// ---------------- K1 (merged): wt-normalize + styles + ka table -------------
__global__ void k_pre(const float* __restrict__ cw,
                      const float* __restrict__ w,
                      const float* __restrict__ aw,
                      const float* __restrict__ ab) {
    __shared__ float red[256];
    __shared__ float rsh;
    if (blockIdx.x < 512) {
        int o = blockIdx.x;
        const float* src = cw + (size_t)o * KTOT;
        float ss = 0.f;
        for (int e = threadIdx.x; e < KTOT; e += 256) {
            float v = src[e]; ss = fmaf(v, v, ss);
        }
        red[threadIdx.x] = ss; __syncthreads();
        for (int s = 128; s > 0; s >>= 1) {
            if (threadIdx.x < s) red[threadIdx.x] += red[threadIdx.x + s];
            __syncthreads();
        }
        if (threadIdx.x == 0) rsh = rsqrtf(red[0] * (1.0f / 4608.0f));
        __syncthreads();
        float r = rsh;
        for (int e = threadIdx.x; e < KTOT; e += 256)
            g_wtB[(size_t)o * KTOT + e] = __float2half_rn(src[e] * r);
        float r2 = r * r;
        for (int i = threadIdx.x; i < 512; i += 256) {
            float s9 = 0.f;
            #pragma unroll
            for (int k = 0; k < 9; k++) { float v = src[i * 9 + k]; s9 = fmaf(v, v, s9); }
            g_A[o * 512 + i] = s9 * r2;
        }
    } else if (blockIdx.x < 1024) {
        int wid = ((blockIdx.x - 512) * 256 + threadIdx.x) >> 5;
        int lane = threadIdx.x & 31;
        int b = wid >> 9, c = wid & 511;
        const float* wr = w + b * 512;
        const float* ar = aw + c * 512;
        float acc = 0.f;
        #pragma unroll 4
        for (int d = lane; d < 512; d += 32) acc = fmaf(wr[d], ar[d], acc);
        #pragma unroll
        for (int s = 16; s; s >>= 1) acc += __shfl_xor_sync(0xFFFFFFFFu, acc, s);
        if (lane == 0) g_styles[wid] = acc * 0.04419417382415922f + ab[c];
    } else {
        int k = (blockIdx.x - 1024) * 256 + threadIdx.x;
        if (k < KTOT) {
            int ci = k / 9; int t9 = k - 9 * ci;
            int ky = t9 / 3; int kx = t9 - 3 * ky;
            g_ka[k] = (u32)kx * (BATCH * (u32)BSZ) + (u32)(ci * CISZ + ky * 72);
        }
    }
}

// ---------------- K2: normalize styles --------------------------------------
__global__ void k_norm_styles() {
    __shared__ float red[256];
    float ss = 0.f;
    for (int i = threadIdx.x; i < 4096; i += 256) {
        float v = g_styles[i]; ss = fmaf(v, v, ss);
    }
    red[threadIdx.x] = ss; __syncthreads();
    for (int s = 128; s > 0; s >>= 1) {
        if (threadIdx.x < s) red[threadIdx.x] += red[threadIdx.x + s];
        __syncthreads();
    }
    float g = rsqrtf(red[0] * (1.0f / 4096.0f));
    for (int i = threadIdx.x; i < 4096; i += 256) g_s[i] = g_styles[i] * g;
}

// ---------------- K3: padded+scaled+shifted images (3 kx copies) -------------
__device__ __forceinline__ __half pval(const float* __restrict__ x, int b, int q) {
    if (q < 0) return __float2half_rn(0.f);
    int ci = q / CISZ; int j = q - ci * CISZ;
    int rr = j / 72;   int cc = j - rr * 72;
    float v = 0.f;
    if (rr >= 2 && rr < 66 && cc < 64) {
        int cf = b * 512 + ci;
        v = x[(((size_t)cf << 6) + (rr - 2)) * 64 + cc] * g_s[cf];
    }
    return __float2half_rn(v);
}
__global__ void k_pad(const float* __restrict__ x) {
    int i2 = blockIdx.x * 256 + threadIdx.x;   // u32 index, < BSZ/2
    int s = blockIdx.y, b = blockIdx.z;
    int q0 = 2 * i2 + s - 2;
    __half v0 = pval(x, b, q0);
    __half v1 = pval(x, b, q0 + 1);
    ((__half2*)g_xp)[((size_t)(s * BATCH + b) * BSZ >> 1) + i2] = __halves2half2(v0, v1);
}

// ---------------- K4: pure-GEMM fp16 HMMA conv, K-chunk 64, 2-stage ----------
// Block 128 p' x 128 o; 8 warps (4m x 2n); 72 chunks of K=64.
// As: [2][64 krows][136 halves] (pitch 272B); Bs: [2][128 o][72 halves] (144B).
#define ASTG 17408
#define BSTG 18432
#define CONV_SMEM (2 * (ASTG + BSTG))   // 71680

__global__ __launch_bounds__(256, 2) void k_conv() {
    extern __shared__ __align__(16) char dsm[];
    int tid = threadIdx.x, wid = tid >> 5, lane = tid & 31;
    int g = lane >> 2, tg = lane & 3;
    int wm = wid & 3, wn = wid >> 2;
    int b = blockIdx.z;
    int p0 = blockIdx.x * 128, o0 = blockIdx.y * 128;

    u32 AsB[2] = { smem_u32(dsm),            smem_u32(dsm) + ASTG };
    u32 BsB[2] = { smem_u32(dsm) + 2 * ASTG, smem_u32(dsm) + 2 * ASTG + BSTG };
    u64 xpg = gmem_u64(g_xp) + ((u64)((u32)b * (u32)BSZ) + (u32)p0) * 2;
    u64 wg  = gmem_u64(g_wtB);

    // ldmatrix addresses
    u32 a_base = (u32)(((((lane >> 4) << 3) + (lane & 7)) * 272)
                       + wm * 64 + ((lane >> 3) & 1) * 16);
    u32 b_off[4];
    #pragma unroll
    for (int q = 0; q < 4; q++) {
        int row = wn * 64 + q * 16 + ((lane >> 3) >> 1) * 8 + (lane & 7);
        b_off[q] = (u32)(row * 144 + ((lane >> 3) & 1) * 16);
    }

    float acc[2][8][4];
    #pragma unroll
    for (int mt = 0; mt < 2; mt++)
        #pragma unroll
        for (int nt = 0; nt < 8; nt++)
            #pragma unroll
            for (int q = 0; q < 4; q++) acc[mt][nt][q] = 0.f;

    auto stage = [&](int j, int buf) {
        int k0s = j * 64;
        // A: 64 k-rows x 256B = 1024 cpa16 (4/thread)
        #pragma unroll
        for (int q = 0; q < 4; q++) {
            int idx = tid + q * 256;
            int kk = idx >> 4, seg = idx & 15;
            u32 ka = g_ka[k0s + kk];
            cpa16(AsB[buf] + (u32)(kk * 272 + seg * 16),
                  xpg + ((u64)ka + (u32)(seg * 8)) * 2);
        }
        // B: 128 rows x 128B = 1024 cpa16 (4/thread)
        #pragma unroll
        for (int q = 0; q < 4; q++) {
            int idx = tid + q * 256;
            int br = idx >> 3, bs = idx & 7;
            cpa16(BsB[buf] + (u32)(br * 144 + bs * 16),
                  wg + ((u64)(u32)(o0 + br) * KTOT + (u32)(k0s + bs * 8)) * 2);
        }
        cpa_commit();
    };

    stage(0, 0);

    for (int i = 0; i < 72; i++) {
        int cur = i & 1;
        if (i + 1 < 72) { stage(i + 1, cur ^ 1); cpa_wait<1>(); }
        else            { cpa_wait<0>(); }
        __syncthreads();

        #pragma unroll
        for (int sl = 0; sl < 4; sl++) {
            u32 af[2][4];
            #pragma unroll
            for (int mt = 0; mt < 2; mt++)
                ldsm4t(af[mt][0], af[mt][1], af[mt][2], af[mt][3],
                       AsB[cur] + a_base + (u32)(mt * 32) + (u32)(sl * 16 * 272));
            u32 bf[8][2];
            #pragma unroll
            for (int q = 0; q < 4; q++) {
                u32 r0, r1, r2, r3;
                ldsm4(r0, r1, r2, r3, BsB[cur] + b_off[q] + (u32)(sl * 32));
                bf[2 * q][0] = r0; bf[2 * q][1] = r1;
                bf[2 * q + 1][0] = r2; bf[2 * q + 1][1] = r3;
            }
            #pragma unroll
            for (int mt = 0; mt < 2; mt++)
                #pragma unroll
                for (int nt = 0; nt < 8; nt++)
                    mma_f16(acc[mt][nt], af[mt][0], af[mt][1], af[mt][2], af[mt][3],
                            bf[nt][0], bf[nt][1]);
        }
        __syncthreads();   // reads of buf cur complete before restage
    }

    // ---- epilogue: store to padded g_y ----
    #pragma unroll
    for (int mt = 0; mt < 2; mt++) {
        int pA = p0 + wm * 32 + mt * 16 + g;
        int pB = pA + 8;
        bool okA = (pA < MPAD) && (pA % 72) < 66;
        bool okB = (pB < MPAD) && (pB % 72) < 66;
        #pragma unroll
        for (int nt = 0; nt < 8; nt++) {
            int o = o0 + wn * 64 + nt * 8 + 2 * tg;
            size_t bo = ((size_t)(b * 512 + o)) * MPAD;
            if (okA) {
                g_y[bo + pA] = acc[mt][nt][0];
                g_y[bo + MPAD + pA] = acc[mt][nt][1];
            }
            if (okB) {
                g_y[bo + pB] = acc[mt][nt][2];
                g_y[bo + MPAD + pB] = acc[mt][nt][3];
            }
        }
    }
}

// ---------------- K5: demod --------------------------------------------------
__global__ void k_demod() {
    int wid = (blockIdx.x * 256 + threadIdx.x) >> 5;
    int lane = threadIdx.x & 31;
    int b = wid >> 9, o = wid & 511;
    const float* Ao = g_A + o * 512;
    const float* sbp = g_s + b * 512;
    float acc = 0.f;
    #pragma unroll 4
    for (int i = lane; i < 512; i += 32) {
        float sv = sbp[i]; acc = fmaf(Ao[i], sv * sv, acc);
    }
    #pragma unroll
    for (int s = 16; s; s >>= 1) acc += __shfl_xor_sync(0xFFFFFFFFu, acc, s);
    if (lane == 0) g_d[wid] = rsqrtf(acc + 1e-8f);
}

// ---------------- K6: demod+bias -> up-FIR -> act -> down-FIR ----------------
__global__ __launch_bounds__(256) void k_fir(const float* __restrict__ upf,
                                             const float* __restrict__ dnf,
                                             const float* __restrict__ cb,
                                             float* __restrict__ out) {
    extern __shared__ float sm[];
    float* sfu  = sm;
    float* sfd  = sm + 12;
    float* simg = sm + 24;
    float* wbuf = simg + 4356;
    float* smid = wbuf + 8 * 204;
    int blk = blockIdx.x;
    int tid = threadIdx.x;
    const float* src = g_y + (size_t)blk * MPAD;
    float dm = g_d[blk];
    float bias = cb[blk & 511];

    if (tid < 12) { sfu[tid] = 2.0f * upf[11 - tid]; sfd[tid] = dnf[11 - tid]; }
    for (int e = tid; e < NPIX; e += 256) {
        int r = e / 66, c = e - 66 * r;
        simg[e] = src[r * 72 + c] * dm + bias;
    }
    __syncthreads();

    int warp = tid >> 5, lane = tid & 31;
    float* vrow = wbuf + warp * 204;
    float* hrow = vrow + 66;

    for (int rr = warp; rr < SUP; rr += 8) {
        int tv0 = (rr & 1) ^ 1;
        for (int c = lane; c < 66; c += 32) {
            float a = 0.f;
            for (int t = tv0; t < 12; t += 2) {
                int j = rr + t - 9;
                if (j >= 0 && j <= 130) a = fmaf(sfu[t], simg[(j >> 1) * 66 + c], a);
            }
            vrow[c] = a;
        }
        __syncwarp();
        for (int q = lane; q < SUP; q += 32) {
            float a = 0.f;
            int t0 = (q & 1) ^ 1;
            for (int t = t0; t < 12; t += 2) {
                int j = q + t - 9;
                if (j >= 0 && j <= 130) a = fmaf(sfu[t], vrow[j >> 1], a);
            }
            a = (a >= 0.f ? a : 0.2f * a) * 1.4142135623730951f;
            a = fminf(fmaxf(a, -256.f), 256.f);
            hrow[q] = a;
        }
        __syncwarp();
        for (int p2 = lane; p2 < 64; p2 += 32) {
            float a = 0.f;
            #pragma unroll
            for (int t = 0; t < 12; t++) a = fmaf(sfd[t], hrow[2 * p2 + t], a);
            smid[rr * 64 + p2] = a;
        }
        __syncwarp();
    }
    __syncthreads();

    float* dst = out + (size_t)blk * 4096;
    for (int e = tid; e < 4096; e += 256) {
        int p2 = e >> 6, c = e & 63;
        float a = 0.f;
        #pragma unroll
        for (int t = 0; t < 12; t++) a = fmaf(sfd[t], smid[(2 * p2 + t) * 64 + c], a);
        dst[e] = a;
    }
}

// ---------------- launch -----------------------------------------------------
extern "C" void kernel_launch(void* const* d_in, const int* in_sizes, int n_in,
                              void* d_out, int out_size) {
    const float* x  = (const float*)d_in[0];
    const float* w  = (const float*)d_in[1];
    const float* aw = (const float*)d_in[2];
    const float* ab = (const float*)d_in[3];
    const float* cw = (const float*)d_in[4];
    const float* cb = (const float*)d_in[5];
    const float* uf = (const float*)d_in[6];
    const float* df = (const float*)d_in[7];
    float* out = (float*)d_out;

    k_pre<<<1042, 256>>>(cw, w, aw, ab);            // 1 (wt + styles + ka)
    k_norm_styles<<<1, 256>>>();                    // 2

    dim3 pgrid(BSZ / 512, 3, BATCH);                // 3
    k_pad<<<pgrid, 256>>>(x);

    cudaFuncSetAttribute(k_conv, cudaFuncAttributeMaxDynamicSharedMemorySize, CONV_SMEM);
    dim3 cgrid(38, 4, BATCH);
    k_conv<<<cgrid, 256, CONV_SMEM>>>();            // 4 <-- profiled slot

    k_demod<<<512, 256>>>();                        // 5

    const int fir_smem = (24 + 4356 + 8 * 204 + 8832) * (int)sizeof(float);
    cudaFuncSetAttribute(k_fir, cudaFuncAttributeMaxDynamicSharedMemorySize, fir_smem);
    k_fir<<<BATCH * CH, 256, fir_smem>>>(uf, df, cb, out); // 6
}

// round 12
// speedup vs baseline: 1.4990x; 1.4990x over previous
#include <cuda_runtime.h>
#include <cuda_fp16.h>
#include <math.h>

#define BATCH 8
#define CH    512
#define NPIX  4356          // 66*66 valid pixels
#define MPAD  4752          // 66 rows * 72 padded cols
#define SUP   138
#define KTOT  4608
#define CISZ  5040          // per-ci padded image: 70 rows * 72 cols (halves)
#define BSZ   (512 * CISZ)  // per-batch padded image halves = 2,580,480

typedef unsigned int u32;
typedef unsigned long long u64;

// ---------------- scratch (device globals; zero-initialized) ----------------
__device__ float g_styles[BATCH * CH];
__device__ float g_s[BATCH * CH];
__device__ __align__(16) __half g_xp[3 * BATCH * (size_t)BSZ];    // 3 kx-shifted padded imgs
__device__ __align__(16) __half g_wtB[(size_t)CH * KTOT];         // half(wt) [o][k]
__device__ u32 g_ka[KTOT];                                        // k -> halves offset
__device__ float g_A[CH * CH];
__device__ float g_d[BATCH * CH];
__device__ __align__(16) float g_y[(size_t)BATCH * CH * MPAD];    // conv out [b][o][p']

__device__ __forceinline__ void ldsm4(u32& r0, u32& r1, u32& r2, u32& r3, u32 addr) {
    asm volatile("ldmatrix.sync.aligned.m8n8.x4.shared.b16 {%0,%1,%2,%3}, [%4];"
        : "=r"(r0), "=r"(r1), "=r"(r2), "=r"(r3) : "r"(addr));
}
__device__ __forceinline__ void ldsm4t(u32& r0, u32& r1, u32& r2, u32& r3, u32 addr) {
    asm volatile("ldmatrix.sync.aligned.m8n8.x4.trans.shared.b16 {%0,%1,%2,%3}, [%4];"
        : "=r"(r0), "=r"(r1), "=r"(r2), "=r"(r3) : "r"(addr));
}
__device__ __forceinline__ void mma_f16(float* c, u32 a0, u32 a1, u32 a2, u32 a3,
                                        u32 b0, u32 b1) {
    asm volatile("mma.sync.aligned.m16n8k16.row.col.f32.f16.f16.f32 "
        "{%0,%1,%2,%3}, {%4,%5,%6,%7}, {%8,%9}, {%0,%1,%2,%3};"
        : "+f"(c[0]), "+f"(c[1]), "+f"(c[2]), "+f"(c[3])
        : "r"(a0), "r"(a1), "r"(a2), "r"(a3), "r"(b0), "r"(b1));
}
__device__ __forceinline__ u32 smem_u32(const void* p) {
    u32 a; asm("{ .reg .u64 t; cvta.to.shared.u64 t, %1; cvt.u32.u64 %0, t; }"
               : "=r"(a) : "l"(p));
    return a;
}
__device__ __forceinline__ u64 gmem_u64(const void* p) {
    u64 a; asm("cvta.to.global.u64 %0, %1;" : "=l"(a) : "l"(p));
    return a;
}
__device__ __forceinline__ void cpa16(u32 dst, u64 src) {
    asm volatile("cp.async.cg.shared.global [%0], [%1], 16;"
                 :: "r"(dst), "l"(src) : "memory");
}
__device__ __forceinline__ void cpa_commit() {
    asm volatile("cp.async.commit_group;" ::: "memory");
}
template <int N> __device__ __forceinline__ void cpa_wait() {
    asm volatile("cp.async.wait_group %0;" :: "n"(N) : "memory");
}

// ---------------- K1 (merged): wt-normalize + styles + ka table -------------
__global__ void k_pre(const float* __restrict__ cw,
                      const float* __restrict__ w,
                      const float* __restrict__ aw,
                      const float* __restrict__ ab) {
    __shared__ float red[256];
    __shared__ float rsh;
    if (blockIdx.x < 512) {
        int o = blockIdx.x;
        const float* src = cw + (size_t)o * KTOT;
        float ss = 0.f;
        for (int e = threadIdx.x; e < KTOT; e += 256) {
            float v = src[e]; ss = fmaf(v, v, ss);
        }
        red[threadIdx.x] = ss; __syncthreads();
        for (int s = 128; s > 0; s >>= 1) {
            if (threadIdx.x < s) red[threadIdx.x] += red[threadIdx.x + s];
            __syncthreads();
        }
        if (threadIdx.x == 0) rsh = rsqrtf(red[0] * (1.0f / 4608.0f));
        __syncthreads();
        float r = rsh;
        for (int e = threadIdx.x; e < KTOT; e += 256)
            g_wtB[(size_t)o * KTOT + e] = __float2half_rn(src[e] * r);
        float r2 = r * r;
        for (int i = threadIdx.x; i < 512; i += 256) {
            float s9 = 0.f;
            #pragma unroll
            for (int k = 0; k < 9; k++) { float v = src[i * 9 + k]; s9 = fmaf(v, v, s9); }
            g_A[o * 512 + i] = s9 * r2;
        }
    } else if (blockIdx.x < 1024) {
        int wid = ((blockIdx.x - 512) * 256 + threadIdx.x) >> 5;
        int lane = threadIdx.x & 31;
        int b = wid >> 9, c = wid & 511;
        const float* wr = w + b * 512;
        const float* ar = aw + c * 512;
        float acc = 0.f;
        #pragma unroll 4
        for (int d = lane; d < 512; d += 32) acc = fmaf(wr[d], ar[d], acc);
        #pragma unroll
        for (int s = 16; s; s >>= 1) acc += __shfl_xor_sync(0xFFFFFFFFu, acc, s);
        if (lane == 0) g_styles[wid] = acc * 0.04419417382415922f + ab[c];
    } else {
        int k = (blockIdx.x - 1024) * 256 + threadIdx.x;
        if (k < KTOT) {
            int ci = k / 9; int t9 = k - 9 * ci;
            int ky = t9 / 3; int kx = t9 - 3 * ky;
            g_ka[k] = (u32)kx * (BATCH * (u32)BSZ) + (u32)(ci * CISZ + ky * 72);
        }
    }
}

// ---------------- K2: normalize styles --------------------------------------
__global__ void k_norm_styles() {
    __shared__ float red[256];
    float ss = 0.f;
    for (int i = threadIdx.x; i < 4096; i += 256) {
        float v = g_styles[i]; ss = fmaf(v, v, ss);
    }
    red[threadIdx.x] = ss; __syncthreads();
    for (int s = 128; s > 0; s >>= 1) {
        if (threadIdx.x < s) red[threadIdx.x] += red[threadIdx.x + s];
        __syncthreads();
    }
    float g = rsqrtf(red[0] * (1.0f / 4096.0f));
    for (int i = threadIdx.x; i < 4096; i += 256) g_s[i] = g_styles[i] * g;
}

// ---------------- K3: one-pass padded+scaled images, 3 kx shifts -------------
// Block (i2-chunk, ci, b). Thread handles half2 pair j = 2*i2 of Pfull[ci]:
//   Pfull local (rr,cc): value x[rr-2][cc]*s for rr in [2,66), cc<64, else 0.
// Writes: C2[j] = (v0,v1); C0[j+2] = (v0,v1); C1[j] = (prev, v0) via shfl.
__global__ void k_pad(const float* __restrict__ x) {
    int i2 = blockIdx.x * 256 + threadIdx.x;       // < 2560, valid < 2520
    int ci = blockIdx.y, b = blockIdx.z;
    if (i2 >= 2520) return;
    int rr = i2 / 36;            // 0..69
    int cc = 2 * (i2 - rr * 36); // 0..70 even
    float s = g_s[b * 512 + ci];
    bool rok = (rr >= 2) & (rr < 66);
    float v0 = 0.f, v1 = 0.f;
    if (rok && cc < 64) {
        float2 xv = *(const float2*)&x[(((size_t)(b * 512 + ci)) * 64 + (rr - 2)) * 64 + cc];
        v0 = xv.x * s; v1 = xv.y * s;
    }
    // previous element Pfull[j-1]: (rr, cc-1) or (rr-1, 71)->0
    float pv = 0.f;
    if (rok && cc > 0 && cc - 1 < 64)
        pv = x[(((size_t)(b * 512 + ci)) * 64 + (rr - 2)) * 64 + (cc - 1)] * s;
    float pv_sh = __shfl_up_sync(0xFFFFFFFFu, v1, 1);
    if ((threadIdx.x & 31) != 0) pv = pv_sh;       // lane>0: neighbor's v1

    __half2 pair  = __floats2half2_rn(v0, v1);
    __half2 pair1 = __floats2half2_rn(pv, v0);
    int j = 2 * i2;
    u32 base = (u32)(ci * CISZ + j);
    __half2* xp2 = (__half2*)g_xp;
    size_t b2 = ((size_t)b * BSZ) >> 1;
    size_t img = (size_t)BATCH * BSZ >> 1;         // halves per copy / 2
    // C2 (kx=2): aligned
    xp2[2 * img + b2 + (base >> 1)] = pair;
    // C0 (kx=0): shifted +2 halves (guard last element of last ci)
    if (!(ci == 511 && i2 == 2519))
        xp2[b2 + ((base + 2) >> 1)] = pair;
    // C1 (kx=1): pair (Pfull[j-1], Pfull[j])
    xp2[img + b2 + (base >> 1)] = pair1;
}

// ---------------- K4: pure-GEMM fp16 HMMA conv, K=32 chunks, 4-stage ---------
// Block 128 p' x 128 o; 8 warps (4m x 2n); 144 chunks of K=32.
// As: [4][32 krows][136 halves] (272B pitch); Bs: [4][128 o][40 halves] (80B).
#define ASTG 8704
#define BSTG 10240
#define CONV_SMEM (4 * (ASTG + BSTG))   // 75776

__global__ __launch_bounds__(256, 2) void k_conv() {
    extern __shared__ __align__(16) char dsm[];
    int tid = threadIdx.x, wid = tid >> 5, lane = tid & 31;
    int g = lane >> 2, tg = lane & 3;
    int wm = wid & 3, wn = wid >> 2;
    int b = blockIdx.z;
    int p0 = blockIdx.x * 128, o0 = blockIdx.y * 128;

    u32 sb = smem_u32(dsm);
    u32 AsB[4], BsB[4];
    #pragma unroll
    for (int s = 0; s < 4; s++) {
        AsB[s] = sb + s * ASTG;
        BsB[s] = sb + 4 * ASTG + s * BSTG;
    }
    u64 xpg = gmem_u64(g_xp) + ((u64)((u32)b * (u32)BSZ) + (u32)p0) * 2;
    u64 wg  = gmem_u64(g_wtB);

    u32 a_base = (u32)(((((lane >> 4) << 3) + (lane & 7)) * 272)
                       + wm * 64 + ((lane >> 3) & 1) * 16);
    u32 b_off[4];
    #pragma unroll
    for (int q = 0; q < 4; q++) {
        int row = wn * 64 + q * 16 + ((lane >> 3) >> 1) * 8 + (lane & 7);
        b_off[q] = (u32)(row * 80 + ((lane >> 3) & 1) * 16);
    }

    float acc[2][8][4];
    #pragma unroll
    for (int mt = 0; mt < 2; mt++)
        #pragma unroll
        for (int nt = 0; nt < 8; nt++)
            #pragma unroll
            for (int q = 0; q < 4; q++) acc[mt][nt][q] = 0.f;

    auto stage = [&](int j, int buf) {
        int k0s = j * 32;
        // A: 32 k-rows x 256B = 512 cpa16 (2/thread)
        #pragma unroll
        for (int q = 0; q < 2; q++) {
            int idx = tid + q * 256;
            int kk = idx >> 4, seg = idx & 15;
            u32 ka = g_ka[k0s + kk];
            cpa16(AsB[buf] + (u32)(kk * 272 + seg * 16),
                  xpg + ((u64)ka + (u32)(seg * 8)) * 2);
        }
        // B: 128 rows x 64B = 512 cpa16 (2/thread)
        #pragma unroll
        for (int q = 0; q < 2; q++) {
            int idx = tid + q * 256;
            int br = idx >> 2, bs = idx & 3;
            cpa16(BsB[buf] + (u32)(br * 80 + bs * 16),
                  wg + ((u64)(u32)(o0 + br) * KTOT + (u32)(k0s + bs * 8)) * 2);
        }
        cpa_commit();
    };

    stage(0, 0); stage(1, 1); stage(2, 2);

    for (int i = 0; i < 144; i++) {
        int cur = i & 3;
        if (i + 3 < 144) { stage(i + 3, (i + 3) & 3); cpa_wait<3>(); }
        else if (i == 141) cpa_wait<2>();
        else if (i == 142) cpa_wait<1>();
        else               cpa_wait<0>();
        __syncthreads();

        #pragma unroll
        for (int sl = 0; sl < 2; sl++) {
            u32 af[2][4];
            #pragma unroll
            for (int mt = 0; mt < 2; mt++)
                ldsm4t(af[mt][0], af[mt][1], af[mt][2], af[mt][3],
                       AsB[cur] + a_base + (u32)(mt * 32) + (u32)(sl * 16 * 272));
            u32 bf[8][2];
            #pragma unroll
            for (int q = 0; q < 4; q++) {
                u32 r0, r1, r2, r3;
                ldsm4(r0, r1, r2, r3, BsB[cur] + b_off[q] + (u32)(sl * 32));
                bf[2 * q][0] = r0; bf[2 * q][1] = r1;
                bf[2 * q + 1][0] = r2; bf[2 * q + 1][1] = r3;
            }
            #pragma unroll
            for (int mt = 0; mt < 2; mt++)
                #pragma unroll
                for (int nt = 0; nt < 8; nt++)
                    mma_f16(acc[mt][nt], af[mt][0], af[mt][1], af[mt][2], af[mt][3],
                            bf[nt][0], bf[nt][1]);
        }
        __syncthreads();   // reads of this buf done before it is re-staged
    }

    // ---- epilogue: store to padded g_y ----
    #pragma unroll
    for (int mt = 0; mt < 2; mt++) {
        int pA = p0 + wm * 32 + mt * 16 + g;
        int pB = pA + 8;
        bool okA = (pA < MPAD) && (pA % 72) < 66;
        bool okB = (pB < MPAD) && (pB % 72) < 66;
        #pragma unroll
        for (int nt = 0; nt < 8; nt++) {
            int o = o0 + wn * 64 + nt * 8 + 2 * tg;
            size_t bo = ((size_t)(b * 512 + o)) * MPAD;
            if (okA) {
                g_y[bo + pA] = acc[mt][nt][0];
                g_y[bo + MPAD + pA] = acc[mt][nt][1];
            }
            if (okB) {
                g_y[bo + pB] = acc[mt][nt][2];
                g_y[bo + MPAD + pB] = acc[mt][nt][3];
            }
        }
    }
}

// ---------------- K5: demod --------------------------------------------------
__global__ void k_demod() {
    int wid = (blockIdx.x * 256 + threadIdx.x) >> 5;
    int lane = threadIdx.x & 31;
    int b = wid >> 9, o = wid & 511;
    const float* Ao = g_A + o * 512;
    const float* sbp = g_s + b * 512;
    float acc = 0.f;
    #pragma unroll 4
    for (int i = lane; i < 512; i += 32) {
        float sv = sbp[i]; acc = fmaf(Ao[i], sv * sv, acc);
    }
    #pragma unroll
    for (int s = 16; s; s >>= 1) acc += __shfl_xor_sync(0xFFFFFFFFu, acc, s);
    if (lane == 0) g_d[wid] = rsqrtf(acc + 1e-8f);
}

// ---------------- K6: demod+bias -> up-FIR -> act -> down-FIR ----------------
__global__ __launch_bounds__(256) void k_fir(const float* __restrict__ upf,
                                             const float* __restrict__ dnf,
                                             const float* __restrict__ cb,
                                             float* __restrict__ out) {
    extern __shared__ float sm[];
    float* sfu  = sm;
    float* sfd  = sm + 12;
    float* simg = sm + 24;
    float* wbuf = simg + 4356;
    float* smid = wbuf + 8 * 204;
    int blk = blockIdx.x;
    int tid = threadIdx.x;
    const float* src = g_y + (size_t)blk * MPAD;
    float dm = g_d[blk];
    float bias = cb[blk & 511];

    if (tid < 12) { sfu[tid] = 2.0f * upf[11 - tid]; sfd[tid] = dnf[11 - tid]; }
    for (int e = tid; e < NPIX; e += 256) {
        int r = e / 66, c = e - 66 * r;
        simg[e] = src[r * 72 + c] * dm + bias;
    }
    __syncthreads();

    int warp = tid >> 5, lane = tid & 31;
    float* vrow = wbuf + warp * 204;
    float* hrow = vrow + 66;

    for (int rr = warp; rr < SUP; rr += 8) {
        int tv0 = (rr & 1) ^ 1;
        for (int c = lane; c < 66; c += 32) {
            float a = 0.f;
            for (int t = tv0; t < 12; t += 2) {
                int j = rr + t - 9;
                if (j >= 0 && j <= 130) a = fmaf(sfu[t], simg[(j >> 1) * 66 + c], a);
            }
            vrow[c] = a;
        }
        __syncwarp();
        for (int q = lane; q < SUP; q += 32) {
            float a = 0.f;
            int t0 = (q & 1) ^ 1;
            for (int t = t0; t < 12; t += 2) {
                int j = q + t - 9;
                if (j >= 0 && j <= 130) a = fmaf(sfu[t], vrow[j >> 1], a);
            }
            a = (a >= 0.f ? a : 0.2f * a) * 1.4142135623730951f;
            a = fminf(fmaxf(a, -256.f), 256.f);
            hrow[q] = a;
        }
        __syncwarp();
        for (int p2 = lane; p2 < 64; p2 += 32) {
            float a = 0.f;
            #pragma unroll
            for (int t = 0; t < 12; t++) a = fmaf(sfd[t], hrow[2 * p2 + t], a);
            smid[rr * 64 + p2] = a;
        }
        __syncwarp();
    }
    __syncthreads();

    float* dst = out + (size_t)blk * 4096;
    for (int e = tid; e < 4096; e += 256) {
        int p2 = e >> 6, c = e & 63;
        float a = 0.f;
        #pragma unroll
        for (int t = 0; t < 12; t++) a = fmaf(sfd[t], smid[(2 * p2 + t) * 64 + c], a);
        dst[e] = a;
    }
}

// ---------------- launch -----------------------------------------------------
extern "C" void kernel_launch(void* const* d_in, const int* in_sizes, int n_in,
                              void* d_out, int out_size) {
    const float* x  = (const float*)d_in[0];
    const float* w  = (const float*)d_in[1];
    const float* aw = (const float*)d_in[2];
    const float* ab = (const float*)d_in[3];
    const float* cw = (const float*)d_in[4];
    const float* cb = (const float*)d_in[5];
    const float* uf = (const float*)d_in[6];
    const float* df = (const float*)d_in[7];
    float* out = (float*)d_out;

    k_pre<<<1042, 256>>>(cw, w, aw, ab);            // 1 (wt + styles + ka)
    k_norm_styles<<<1, 256>>>();                    // 2

    dim3 pgrid(10, 512, BATCH);                     // 3 (one-pass pad)
    k_pad<<<pgrid, 256>>>(x);

    cudaFuncSetAttribute(k_conv, cudaFuncAttributeMaxDynamicSharedMemorySize, CONV_SMEM);
    dim3 cgrid(38, 4, BATCH);
    k_conv<<<cgrid, 256, CONV_SMEM>>>();            // 4 <-- profiled slot

    k_demod<<<512, 256>>>();                        // 5

    const int fir_smem = (24 + 4356 + 8 * 204 + 8832) * (int)sizeof(float);
    cudaFuncSetAttribute(k_fir, cudaFuncAttributeMaxDynamicSharedMemorySize, fir_smem);
    k_fir<<<BATCH * CH, 256, fir_smem>>>(uf, df, cb, out); // 6
}

// round 13
// speedup vs baseline: 2.1059x; 1.4048x over previous
#include <cuda_runtime.h>
#include <cuda_fp16.h>
#include <math.h>

#define BATCH 8
#define CH    512
#define NPIX  4356          // 66*66 valid pixels
#define MPAD  4752          // 66 rows * 72 padded cols
#define SUP   138
#define KTOT  4608
#define CISZ  5040          // per-ci padded image: 70 rows * 72 cols (halves)
#define BSZ   (512 * CISZ)  // per-batch padded image halves = 2,580,480

typedef unsigned int u32;
typedef unsigned long long u64;

// ---------------- scratch (device globals; zero-initialized) ----------------
__device__ float g_styles[BATCH * CH];
__device__ float g_s[BATCH * CH];
__device__ __align__(16) __half g_xp[3 * BATCH * (size_t)BSZ];    // 3 kx-shifted padded imgs
__device__ __align__(16) __half g_wtB[(size_t)CH * KTOT];         // half(wt) [o][k]
__device__ u32 g_ka[KTOT];                                        // k -> halves offset
__device__ float g_A[CH * CH];
__device__ float g_d[BATCH * CH];
__device__ __align__(16) float g_y[(size_t)BATCH * CH * MPAD];    // conv out [b][o][p']

__device__ __forceinline__ void ldsm4(u32& r0, u32& r1, u32& r2, u32& r3, u32 addr) {
    asm volatile("ldmatrix.sync.aligned.m8n8.x4.shared.b16 {%0,%1,%2,%3}, [%4];"
        : "=r"(r0), "=r"(r1), "=r"(r2), "=r"(r3) : "r"(addr));
}
__device__ __forceinline__ void ldsm4t(u32& r0, u32& r1, u32& r2, u32& r3, u32 addr) {
    asm volatile("ldmatrix.sync.aligned.m8n8.x4.trans.shared.b16 {%0,%1,%2,%3}, [%4];"
        : "=r"(r0), "=r"(r1), "=r"(r2), "=r"(r3) : "r"(addr));
}
__device__ __forceinline__ void mma_f16(float* c, u32 a0, u32 a1, u32 a2, u32 a3,
                                        u32 b0, u32 b1) {
    asm volatile("mma.sync.aligned.m16n8k16.row.col.f32.f16.f16.f32 "
        "{%0,%1,%2,%3}, {%4,%5,%6,%7}, {%8,%9}, {%0,%1,%2,%3};"
        : "+f"(c[0]), "+f"(c[1]), "+f"(c[2]), "+f"(c[3])
        : "r"(a0), "r"(a1), "r"(a2), "r"(a3), "r"(b0), "r"(b1));
}
__device__ __forceinline__ u32 smem_u32(const void* p) {
    u32 a; asm("{ .reg .u64 t; cvta.to.shared.u64 t, %1; cvt.u32.u64 %0, t; }"
               : "=r"(a) : "l"(p));
    return a;
}
__device__ __forceinline__ u64 gmem_u64(const void* p) {
    u64 a; asm("cvta.to.global.u64 %0, %1;" : "=l"(a) : "l"(p));
    return a;
}
__device__ __forceinline__ void cpa16(u32 dst, u64 src) {
    asm volatile("cp.async.cg.shared.global [%0], [%1], 16;"
                 :: "r"(dst), "l"(src) : "memory");
}
__device__ __forceinline__ void cpa_commit() {
    asm volatile("cp.async.commit_group;" ::: "memory");
}
template <int N> __device__ __forceinline__ void cpa_wait() {
    asm volatile("cp.async.wait_group %0;" :: "n"(N) : "memory");
}

// ---------------- K1 (merged): wt-normalize + styles + ka table -------------
__global__ void k_pre(const float* __restrict__ cw,
                      const float* __restrict__ w,
                      const float* __restrict__ aw,
                      const float* __restrict__ ab) {
    __shared__ float red[256];
    __shared__ float rsh;
    if (blockIdx.x < 512) {
        int o = blockIdx.x;
        const float* src = cw + (size_t)o * KTOT;
        float ss = 0.f;
        for (int e = threadIdx.x; e < KTOT; e += 256) {
            float v = src[e]; ss = fmaf(v, v, ss);
        }
        red[threadIdx.x] = ss; __syncthreads();
        for (int s = 128; s > 0; s >>= 1) {
            if (threadIdx.x < s) red[threadIdx.x] += red[threadIdx.x + s];
            __syncthreads();
        }
        if (threadIdx.x == 0) rsh = rsqrtf(red[0] * (1.0f / 4608.0f));
        __syncthreads();
        float r = rsh;
        for (int e = threadIdx.x; e < KTOT; e += 256)
            g_wtB[(size_t)o * KTOT + e] = __float2half_rn(src[e] * r);
        float r2 = r * r;
        for (int i = threadIdx.x; i < 512; i += 256) {
            float s9 = 0.f;
            #pragma unroll
            for (int k = 0; k < 9; k++) { float v = src[i * 9 + k]; s9 = fmaf(v, v, s9); }
            g_A[o * 512 + i] = s9 * r2;
        }
    } else if (blockIdx.x < 1024) {
        int wid = ((blockIdx.x - 512) * 256 + threadIdx.x) >> 5;
        int lane = threadIdx.x & 31;
        int b = wid >> 9, c = wid & 511;
        const float* wr = w + b * 512;
        const float* ar = aw + c * 512;
        float acc = 0.f;
        #pragma unroll 4
        for (int d = lane; d < 512; d += 32) acc = fmaf(wr[d], ar[d], acc);
        #pragma unroll
        for (int s = 16; s; s >>= 1) acc += __shfl_xor_sync(0xFFFFFFFFu, acc, s);
        if (lane == 0) g_styles[wid] = acc * 0.04419417382415922f + ab[c];
    } else {
        int k = (blockIdx.x - 1024) * 256 + threadIdx.x;
        if (k < KTOT) {
            int ci = k / 9; int t9 = k - 9 * ci;
            int ky = t9 / 3; int kx = t9 - 3 * ky;
            g_ka[k] = (u32)kx * (BATCH * (u32)BSZ) + (u32)(ci * CISZ + ky * 72);
        }
    }
}

// ---------------- K2: normalize styles --------------------------------------
__global__ void k_norm_styles() {
    __shared__ float red[256];
    float ss = 0.f;
    for (int i = threadIdx.x; i < 4096; i += 256) {
        float v = g_styles[i]; ss = fmaf(v, v, ss);
    }
    red[threadIdx.x] = ss; __syncthreads();
    for (int s = 128; s > 0; s >>= 1) {
        if (threadIdx.x < s) red[threadIdx.x] += red[threadIdx.x + s];
        __syncthreads();
    }
    float g = rsqrtf(red[0] * (1.0f / 4096.0f));
    for (int i = threadIdx.x; i < 4096; i += 256) g_s[i] = g_styles[i] * g;
}

// ---------------- K3: one-pass padded+scaled images, 3 kx shifts -------------
__global__ void k_pad(const float* __restrict__ x) {
    int i2 = blockIdx.x * 256 + threadIdx.x;       // < 2560, valid < 2520
    int ci = blockIdx.y, b = blockIdx.z;
    if (i2 >= 2520) return;
    int rr = i2 / 36;            // 0..69
    int cc = 2 * (i2 - rr * 36); // 0..70 even
    float s = g_s[b * 512 + ci];
    bool rok = (rr >= 2) & (rr < 66);
    float v0 = 0.f, v1 = 0.f;
    if (rok && cc < 64) {
        float2 xv = *(const float2*)&x[(((size_t)(b * 512 + ci)) * 64 + (rr - 2)) * 64 + cc];
        v0 = xv.x * s; v1 = xv.y * s;
    }
    float pv = 0.f;
    if (rok && cc > 0 && cc - 1 < 64)
        pv = x[(((size_t)(b * 512 + ci)) * 64 + (rr - 2)) * 64 + (cc - 1)] * s;
    float pv_sh = __shfl_up_sync(0xFFFFFFFFu, v1, 1);
    if ((threadIdx.x & 31) != 0) pv = pv_sh;

    __half2 pair  = __floats2half2_rn(v0, v1);
    __half2 pair1 = __floats2half2_rn(pv, v0);
    int j = 2 * i2;
    u32 base = (u32)(ci * CISZ + j);
    __half2* xp2 = (__half2*)g_xp;
    size_t b2 = ((size_t)b * BSZ) >> 1;
    size_t img = (size_t)BATCH * BSZ >> 1;
    xp2[2 * img + b2 + (base >> 1)] = pair;
    if (!(ci == 511 && i2 == 2519))
        xp2[b2 + ((base + 2) >> 1)] = pair;
    xp2[img + b2 + (base >> 1)] = pair1;
}

// ---------------- K4: pure-GEMM fp16 HMMA conv, K=32 chunks, 3-stage ---------
#define ASTG 8704
#define BSTG 10240
#define CONV_SMEM (3 * (ASTG + BSTG))   // 56832

__global__ __launch_bounds__(256, 2) void k_conv() {
    extern __shared__ __align__(16) char dsm[];
    int tid = threadIdx.x, wid = tid >> 5, lane = tid & 31;
    int g = lane >> 2, tg = lane & 3;
    int wm = wid & 3, wn = wid >> 2;
    int b = blockIdx.z;
    int p0 = blockIdx.x * 128, o0 = blockIdx.y * 128;

    u32 sb = smem_u32(dsm);
    u32 AsB[3], BsB[3];
    #pragma unroll
    for (int s = 0; s < 3; s++) {
        AsB[s] = sb + s * ASTG;
        BsB[s] = sb + 3 * ASTG + s * BSTG;
    }
    u64 xpg = gmem_u64(g_xp) + ((u64)((u32)b * (u32)BSZ) + (u32)p0) * 2;
    u64 wg  = gmem_u64(g_wtB);

    u32 a_base = (u32)(((((lane >> 4) << 3) + (lane & 7)) * 272)
                       + wm * 64 + ((lane >> 3) & 1) * 16);
    u32 b_off[4];
    #pragma unroll
    for (int q = 0; q < 4; q++) {
        int row = wn * 64 + q * 16 + ((lane >> 3) >> 1) * 8 + (lane & 7);
        b_off[q] = (u32)(row * 80 + ((lane >> 3) & 1) * 16);
    }

    float acc[2][8][4];
    #pragma unroll
    for (int mt = 0; mt < 2; mt++)
        #pragma unroll
        for (int nt = 0; nt < 8; nt++)
            #pragma unroll
            for (int q = 0; q < 4; q++) acc[mt][nt][q] = 0.f;

    auto stage = [&](int j, int buf) {
        int k0s = j * 32;
        #pragma unroll
        for (int q = 0; q < 2; q++) {
            int idx = tid + q * 256;
            int kk = idx >> 4, seg = idx & 15;
            u32 ka = g_ka[k0s + kk];
            cpa16(AsB[buf] + (u32)(kk * 272 + seg * 16),
                  xpg + ((u64)ka + (u32)(seg * 8)) * 2);
        }
        #pragma unroll
        for (int q = 0; q < 2; q++) {
            int idx = tid + q * 256;
            int br = idx >> 2, bs = idx & 3;
            cpa16(BsB[buf] + (u32)(br * 80 + bs * 16),
                  wg + ((u64)(u32)(o0 + br) * KTOT + (u32)(k0s + bs * 8)) * 2);
        }
        cpa_commit();
    };

    stage(0, 0); stage(1, 1);

    int cur = 0, nxt = 2;
    for (int i = 0; i < 144; i++) {
        if (i + 2 < 144) { stage(i + 2, nxt); cpa_wait<2>(); }
        else if (i == 142) cpa_wait<1>();
        else               cpa_wait<0>();
        __syncthreads();

        #pragma unroll
        for (int sl = 0; sl < 2; sl++) {
            u32 af[2][4];
            #pragma unroll
            for (int mt = 0; mt < 2; mt++)
                ldsm4t(af[mt][0], af[mt][1], af[mt][2], af[mt][3],
                       AsB[cur] + a_base + (u32)(mt * 32) + (u32)(sl * 16 * 272));
            u32 bf[8][2];
            #pragma unroll
            for (int q = 0; q < 4; q++) {
                u32 r0, r1, r2, r3;
                ldsm4(r0, r1, r2, r3, BsB[cur] + b_off[q] + (u32)(sl * 32));
                bf[2 * q][0] = r0; bf[2 * q][1] = r1;
                bf[2 * q + 1][0] = r2; bf[2 * q + 1][1] = r3;
            }
            #pragma unroll
            for (int mt = 0; mt < 2; mt++)
                #pragma unroll
                for (int nt = 0; nt < 8; nt++)
                    mma_f16(acc[mt][nt], af[mt][0], af[mt][1], af[mt][2], af[mt][3],
                            bf[nt][0], bf[nt][1]);
        }
        __syncthreads();   // reads of buf cur done before it is re-staged
        cur = (cur == 2) ? 0 : cur + 1;
        nxt = (nxt == 2) ? 0 : nxt + 1;
    }

    // ---- epilogue: store to padded g_y ----
    #pragma unroll
    for (int mt = 0; mt < 2; mt++) {
        int pA = p0 + wm * 32 + mt * 16 + g;
        int pB = pA + 8;
        bool okA = (pA < MPAD) && (pA % 72) < 66;
        bool okB = (pB < MPAD) && (pB % 72) < 66;
        #pragma unroll
        for (int nt = 0; nt < 8; nt++) {
            int o = o0 + wn * 64 + nt * 8 + 2 * tg;
            size_t bo = ((size_t)(b * 512 + o)) * MPAD;
            if (okA) {
                g_y[bo + pA] = acc[mt][nt][0];
                g_y[bo + MPAD + pA] = acc[mt][nt][1];
            }
            if (okB) {
                g_y[bo + pB] = acc[mt][nt][2];
                g_y[bo + MPAD + pB] = acc[mt][nt][3];
            }
        }
    }
}

// ---------------- K5: demod --------------------------------------------------
__global__ void k_demod() {
    int wid = (blockIdx.x * 256 + threadIdx.x) >> 5;
    int lane = threadIdx.x & 31;
    int b = wid >> 9, o = wid & 511;
    const float* Ao = g_A + o * 512;
    const float* sbp = g_s + b * 512;
    float acc = 0.f;
    #pragma unroll 4
    for (int i = lane; i < 512; i += 32) {
        float sv = sbp[i]; acc = fmaf(Ao[i], sv * sv, acc);
    }
    #pragma unroll
    for (int s = 16; s; s >>= 1) acc += __shfl_xor_sync(0xFFFFFFFFu, acc, s);
    if (lane == 0) g_d[wid] = rsqrtf(acc + 1e-8f);
}

// ---------------- K6: fir v2 — padded image, branch-free unrolled taps ------
// smem: sfu 12 | sfd 12 | simgp 76x66 | wbuf 8x216 (vrowp 76 @+0, hrow 138 @+78)
//       | smid 138x64
#define FIR_SMEM ((24 + 5016 + 8 * 216 + 8832) * 4)   // 62400 B

__global__ __launch_bounds__(256) void k_fir(const float* __restrict__ upf,
                                             const float* __restrict__ dnf,
                                             const float* __restrict__ cb,
                                             float* __restrict__ out) {
    extern __shared__ float sm[];
    float* sfu   = sm;
    float* sfd   = sm + 12;
    float* simgp = sm + 24;            // 76 rows x 66 (rows 0-4, 71-75 zero)
    float* wbuf  = simgp + 5016;       // 8 * 216
    float* smid  = wbuf + 8 * 216;     // 138 x 64
    int blk = blockIdx.x;
    int tid = threadIdx.x;
    const float* src = g_y + (size_t)blk * MPAD;
    float dm = g_d[blk];
    float bias = cb[blk & 511];

    if (tid < 12) { sfu[tid] = 2.0f * upf[11 - tid]; sfd[tid] = dnf[11 - tid]; }
    // zero the 10 pad rows (660 elems)
    for (int e = tid; e < 660; e += 256) {
        int r = e / 66, c = e - 66 * r;
        int row = (r < 5) ? r : r + 66;
        simgp[row * 66 + c] = 0.f;
    }
    // fill rows 5..70 with demod+bias applied
    for (int e = tid; e < NPIX; e += 256) {
        int r = e / 66, c = e - 66 * r;
        simgp[(r + 5) * 66 + c] = src[r * 72 + c] * dm + bias;
    }
    int warp = tid >> 5, lane = tid & 31;
    float* vrowp = wbuf + warp * 216;  // 76 floats, pads [0..4],[71..75]
    float* hrow  = vrowp + 78;         // 138 floats
    if (lane < 5) { vrowp[lane] = 0.f; vrowp[71 + lane] = 0.f; }
    __syncthreads();

    for (int rr = warp; rr < SUP; rr += 8) {
        int tv0 = (rr & 1) ^ 1;
        int r0p = ((rr + tv0 - 9) >> 1) + 5;   // 1..69
        float c0 = sfu[tv0],     c1 = sfu[tv0 + 2], c2 = sfu[tv0 + 4];
        float c3 = sfu[tv0 + 6], c4 = sfu[tv0 + 8], c5 = sfu[tv0 + 10];
        for (int c = lane; c < 66; c += 32) {
            const float* sp = simgp + r0p * 66 + c;
            float a =      c0 * sp[0];
            a = fmaf(c1, sp[66],  a);
            a = fmaf(c2, sp[132], a);
            a = fmaf(c3, sp[198], a);
            a = fmaf(c4, sp[264], a);
            a = fmaf(c5, sp[330], a);
            vrowp[5 + c] = a;
        }
        __syncwarp();
        for (int q = lane; q < SUP; q += 32) {
            int tq0 = (q & 1) ^ 1;
            int q0p = ((q + tq0 - 9) >> 1) + 5;   // 1..69
            const float* vp = vrowp + q0p;
            float a =      sfu[tq0]      * vp[0];
            a = fmaf(sfu[tq0 + 2],  vp[1], a);
            a = fmaf(sfu[tq0 + 4],  vp[2], a);
            a = fmaf(sfu[tq0 + 6],  vp[3], a);
            a = fmaf(sfu[tq0 + 8],  vp[4], a);
            a = fmaf(sfu[tq0 + 10], vp[5], a);
            a = (a >= 0.f ? a : 0.2f * a) * 1.4142135623730951f;
            a = fminf(fmaxf(a, -256.f), 256.f);
            hrow[q] = a;
        }
        __syncwarp();
        for (int p2 = lane; p2 < 64; p2 += 32) {
            const float* hp = hrow + 2 * p2;
            float a = sfd[0] * hp[0];
            #pragma unroll
            for (int t = 1; t < 12; t++) a = fmaf(sfd[t], hp[t], a);
            smid[rr * 64 + p2] = a;
        }
        __syncwarp();
    }
    __syncthreads();

    float* dst = out + (size_t)blk * 4096;
    for (int e = tid; e < 4096; e += 256) {
        int p2 = e >> 6, c = e & 63;
        const float* mp = smid + 2 * p2 * 64 + c;
        float a = sfd[0] * mp[0];
        #pragma unroll
        for (int t = 1; t < 12; t++) a = fmaf(sfd[t], mp[t * 64], a);
        dst[e] = a;
    }
}

// ---------------- launch -----------------------------------------------------
extern "C" void kernel_launch(void* const* d_in, const int* in_sizes, int n_in,
                              void* d_out, int out_size) {
    const float* x  = (const float*)d_in[0];
    const float* w  = (const float*)d_in[1];
    const float* aw = (const float*)d_in[2];
    const float* ab = (const float*)d_in[3];
    const float* cw = (const float*)d_in[4];
    const float* cb = (const float*)d_in[5];
    const float* uf = (const float*)d_in[6];
    const float* df = (const float*)d_in[7];
    float* out = (float*)d_out;

    k_pre<<<1042, 256>>>(cw, w, aw, ab);            // 1 (wt + styles + ka)
    k_norm_styles<<<1, 256>>>();                    // 2

    dim3 pgrid(10, 512, BATCH);                     // 3 (one-pass pad)
    k_pad<<<pgrid, 256>>>(x);

    cudaFuncSetAttribute(k_conv, cudaFuncAttributeMaxDynamicSharedMemorySize, CONV_SMEM);
    dim3 cgrid(38, 4, BATCH);
    k_conv<<<cgrid, 256, CONV_SMEM>>>();            // 4 <-- profiled slot

    k_demod<<<512, 256>>>();                        // 5

    cudaFuncSetAttribute(k_fir, cudaFuncAttributeMaxDynamicSharedMemorySize, FIR_SMEM);
    k_fir<<<BATCH * CH, 256, FIR_SMEM>>>(uf, df, cb, out); // 6
}